// round 1
// baseline (speedup 1.0000x reference)
#include <cuda_runtime.h>
#include <math.h>
#include <stdint.h>

// ---------------- problem constants ----------------
#define BB 4
#define NN 1024
#define DIMM 1024
#define HH 16
#define DH 64
#define NUM_MEM 64
#define JJ (NN + NUM_MEM)   // 1088
#define TOPKK 64
#define SCALEF 0.125f
#define NEGMAX (-3.402823466e38f)
#define JROW 1089           // padded row stride in shared (avoid 16-way bank conflicts)

// ---------------- device scratch (allocation-free) ----------------
__device__ float g_q  [(size_t)BB*HH*NN*DH];     // 16.8 MB
__device__ float g_k  [(size_t)BB*HH*JJ*DH];     // 17.8 MB
__device__ float g_v  [(size_t)BB*HH*JJ*DH];     // 17.8 MB
__device__ float g_raw[(size_t)BB*HH*NN*JJ];     // 285 MB  (raw dots, later reused as post-mixed attn)
__device__ float g_mix[(size_t)BB*HH*NN*JJ];     // 285 MB  (pre-mixed + masked dots)
__device__ float g_ctx[(size_t)BB*NN*DIMM];      // 16.8 MB (attn output, [b,n,h*64+d])

// monotone fp32 -> uint32 key (order-preserving)
__device__ __forceinline__ unsigned fkey(float f) {
    unsigned u = __float_as_uint(f);
    return (u & 0x80000000u) ? ~u : (u | 0x80000000u);
}

// ---------------- kernel 1: broadcast memory K/V into the kv cache ----------------
__global__ void fill_mem_kernel(const float* __restrict__ mk, const float* __restrict__ mv) {
    int idx = blockIdx.x * blockDim.x + threadIdx.x;   // over H*NUM_MEM*DH = 65536
    if (idx >= HH * NUM_MEM * DH) return;
    int h    = idx / (NUM_MEM * DH);
    int rest = idx % (NUM_MEM * DH);                   // j*DH + d
    float kv = mk[idx], vv = mv[idx];
#pragma unroll
    for (int b = 0; b < BB; b++) {
        size_t o = ((size_t)(b * HH + h) * JJ) * DH + rest;
        g_k[o] = kv;
        g_v[o] = vv;
    }
}

// ---------------- kernel 2: 128x128x8 fp32 SGEMM, C = A @ B^T (+bias), scatter epilogues
// EPI 0: scatter into g_q   [b,h,pos,d]
// EPI 1: scatter into g_k   [b,h,NUM_MEM+pos,d]
// EPI 3: scatter into g_v   [b,h,NUM_MEM+pos,d]
// EPI 2: A = g_ctx, row-major C + bias  (final output projection)
// Fixed sizes: M=4096, N=1024, K=1024. grid = (8, 32)
template <int EPI>
__global__ __launch_bounds__(256, 2)
void sgemm128(const float* __restrict__ A, const float* __restrict__ Bw,
              const float* __restrict__ bias, float* __restrict__ C) {
    const int K = 1024;
    const float* Ap = (EPI == 2) ? (const float*)g_ctx : A;

    const int bm = blockIdx.y * 128;
    const int bn = blockIdx.x * 128;

    __shared__ float As[8][128];
    __shared__ float Bs[8][128];

    const int tid = threadIdx.x;
    const int tx = tid & 15, ty = tid >> 4;
    const int lr = tid >> 1;            // 0..127
    const int lk = (tid & 1) * 4;       // 0 or 4

    const float* Ald = Ap + (size_t)(bm + lr) * K + lk;
    const float* Bld = Bw + (size_t)(bn + lr) * K + lk;

    float acc[8][8];
#pragma unroll
    for (int i = 0; i < 8; i++)
#pragma unroll
        for (int j = 0; j < 8; j++) acc[i][j] = 0.f;

    for (int kt = 0; kt < K; kt += 8) {
        float4 av = *(const float4*)(Ald + kt);
        float4 bv = *(const float4*)(Bld + kt);
        __syncthreads();
        As[lk + 0][lr] = av.x; As[lk + 1][lr] = av.y; As[lk + 2][lr] = av.z; As[lk + 3][lr] = av.w;
        Bs[lk + 0][lr] = bv.x; Bs[lk + 1][lr] = bv.y; Bs[lk + 2][lr] = bv.z; Bs[lk + 3][lr] = bv.w;
        __syncthreads();
#pragma unroll
        for (int kk = 0; kk < 8; kk++) {
            float a[8], b[8];
            *(float4*)(a)     = *(const float4*)(&As[kk][ty * 8]);
            *(float4*)(a + 4) = *(const float4*)(&As[kk][ty * 8 + 4]);
            *(float4*)(b)     = *(const float4*)(&Bs[kk][tx * 8]);
            *(float4*)(b + 4) = *(const float4*)(&Bs[kk][tx * 8 + 4]);
#pragma unroll
            for (int i = 0; i < 8; i++)
#pragma unroll
                for (int j = 0; j < 8; j++) acc[i][j] += a[i] * b[j];
        }
    }

#pragma unroll
    for (int i = 0; i < 8; i++) {
        int m = bm + ty * 8 + i;
#pragma unroll
        for (int j = 0; j < 8; j++) {
            int n = bn + tx * 8 + j;
            if (EPI == 2) {
                C[(size_t)m * 1024 + n] = acc[i][j] + bias[n];
            } else {
                int b = m >> 10, pos = m & 1023;
                int h = n >> 6,  d   = n & 63;
                if (EPI == 0) {
                    g_q[((size_t)(b * HH + h) * NN + pos) * DH + d] = acc[i][j];
                } else if (EPI == 1) {
                    g_k[((size_t)(b * HH + h) * JJ + NUM_MEM + pos) * DH + d] = acc[i][j];
                } else {
                    g_v[((size_t)(b * HH + h) * JJ + NUM_MEM + pos) * DH + d] = acc[i][j];
                }
            }
        }
    }
}

// ---------------- kernel 3: raw dots = SCALE * Q @ K^T per (b,h), 64x64 tiles, causal skip
// grid = (17 j-tiles, 16 i-tiles, 64 bh)
__global__ __launch_bounds__(256)
void dots_gemm() {
    const int bh = blockIdx.z;
    const int i0 = blockIdx.y * 64;
    const int j0 = blockIdx.x * 64;
    if (j0 > i0 + 127) return;    // whole tile above causal diagonal (j > i + 64)

    const float* Qp = g_q + ((size_t)bh * NN + i0) * DH;
    const float* Kp = g_k + ((size_t)bh * JJ + j0) * DH;

    __shared__ float Qs[64][68];  // [d][i]
    __shared__ float Ks[64][68];  // [d][j]

    const int tid = threadIdx.x;
    for (int f = tid; f < 1024; f += 256) {
        int r = f >> 4, dq = (f & 15) << 2;
        float4 q4 = *(const float4*)(Qp + (size_t)r * DH + dq);
        Qs[dq + 0][r] = q4.x; Qs[dq + 1][r] = q4.y; Qs[dq + 2][r] = q4.z; Qs[dq + 3][r] = q4.w;
        float4 k4 = *(const float4*)(Kp + (size_t)r * DH + dq);
        Ks[dq + 0][r] = k4.x; Ks[dq + 1][r] = k4.y; Ks[dq + 2][r] = k4.z; Ks[dq + 3][r] = k4.w;
    }
    __syncthreads();

    const int tx = tid & 15, ty = tid >> 4;
    float acc[4][4];
#pragma unroll
    for (int i = 0; i < 4; i++)
#pragma unroll
        for (int j = 0; j < 4; j++) acc[i][j] = 0.f;

#pragma unroll 8
    for (int d = 0; d < 64; d++) {
        float a[4], b[4];
#pragma unroll
        for (int i = 0; i < 4; i++) a[i] = Qs[d][ty * 4 + i];
#pragma unroll
        for (int j = 0; j < 4; j++) b[j] = Ks[d][tx * 4 + j];
#pragma unroll
        for (int i = 0; i < 4; i++)
#pragma unroll
            for (int j = 0; j < 4; j++) acc[i][j] += a[i] * b[j];
    }

    size_t ob = ((size_t)bh * NN + i0 + ty * 4) * JJ + j0 + tx * 4;
#pragma unroll
    for (int i = 0; i < 4; i++)
#pragma unroll
        for (int j = 0; j < 4; j++)
            g_raw[ob + (size_t)i * JJ + j] = acc[i][j] * SCALEF;
}

// ---------------- kernel 4: pre-softmax talking heads + causal mask ----------------
// block per (b,i): mixed[kk][j] = sum_h raw[h][j] * pre[h][kk]; masked -> -FLT_MAX
__global__ __launch_bounds__(256)
void premix_kernel(const float* __restrict__ pre_proj) {
    const int b = blockIdx.x >> 10;
    const int i = blockIdx.x & 1023;
    __shared__ float pp[256];
    if (threadIdx.x < 256) pp[threadIdx.x] = pre_proj[threadIdx.x];
    __syncthreads();

    const int jmax = i + NUM_MEM;                 // last attendable j (inclusive)
    const size_t base = ((size_t)b * HH * NN + i) * JJ;
    const size_t hs = (size_t)NN * JJ;

    for (int j = threadIdx.x; j < JJ; j += 256) {
        if (j <= jmax) {
            float r[HH];
#pragma unroll
            for (int h = 0; h < HH; h++) r[h] = g_raw[base + (size_t)h * hs + j];
#pragma unroll
            for (int kk = 0; kk < HH; kk++) {
                float s = 0.f;
#pragma unroll
                for (int h = 0; h < HH; h++) s += r[h] * pp[h * HH + kk];
                g_mix[base + (size_t)kk * hs + j] = s;
            }
        } else {
#pragma unroll
            for (int kk = 0; kk < HH; kk++)
                g_mix[base + (size_t)kk * hs + j] = NEGMAX;
        }
    }
}

// ---------------- kernel 5: exact top-k (radix select) + softmax + post-mix ----------------
// block per (b,i); warp w owns head w's row. Result written to g_raw (reused).
__global__ __launch_bounds__(512)
void topk_kernel(const float* __restrict__ post_proj) {
    extern __shared__ float sm[];
    float* rows = sm;                                  // 16 * JROW floats
    unsigned* hist = (unsigned*)(sm + HH * JROW);      // 16 * 256 uints
    __shared__ float s_post[256];

    const int b = blockIdx.x >> 10;
    const int i = blockIdx.x & 1023;
    const int tid = threadIdx.x;
    const int w = tid >> 5, lane = tid & 31;
    if (tid < 256) s_post[tid] = post_proj[tid];

    const int jlen = i + NUM_MEM + 1;                  // valid j count (<= 1088), always >= 65
    float* srow = rows + w * JROW;
    unsigned* myh = hist + w * 256;
    const size_t base = ((size_t)(b * HH + w) * NN + i) * JJ;

    // load row + running max
    float m = NEGMAX;
    for (int j = lane; j < jlen; j += 32) {
        float v = g_mix[base + j];
        srow[j] = v;
        m = fmaxf(m, v);
    }
#pragma unroll
    for (int o = 16; o; o >>= 1) m = fmaxf(m, __shfl_xor_sync(0xffffffffu, m, o));

    // exact radix select of the TOPK-th largest value (64), 4 passes of 8 bits
    unsigned prefix = 0;
    int r = TOPKK;
#pragma unroll
    for (int shift = 24; shift >= 0; shift -= 8) {
        for (int t = lane; t < 256; t += 32) myh[t] = 0;
        __syncwarp();
        unsigned pm = (shift == 24) ? 0u : (0xFFFFFFFFu << (shift + 8));
        for (int j = lane; j < jlen; j += 32) {
            unsigned kx = fkey(srow[j]);
            if ((kx & pm) == prefix) atomicAdd(&myh[(kx >> shift) & 255u], 1u);
        }
        __syncwarp();
        unsigned tot = 0;
#pragma unroll
        for (int t = 0; t < 8; t++) tot += myh[lane * 8 + t];
        unsigned s = tot;                               // suffix sum over lanes (lane..31)
#pragma unroll
        for (int o = 1; o < 32; o <<= 1) {
            unsigned tt = __shfl_down_sync(0xffffffffu, s, o);
            if (lane + o < 32) s += tt;
        }
        unsigned s_strict = s - tot;                    // count strictly above this lane's bins
        bool sel = ((unsigned)r > s_strict) && ((unsigned)r <= s);
        unsigned bal = __ballot_sync(0xffffffffu, sel);
        int sl = __ffs(bal) - 1;
        unsigned pick = 0; int newr = r;
        if (sel) {
            int rr = r - (int)s_strict;
#pragma unroll
            for (int t = 7; t >= 0; t--) {              // scan bins high -> low
                unsigned c = myh[lane * 8 + t];
                if (rr <= (int)c) { pick = (unsigned)(lane * 8 + t); newr = rr; break; }
                rr -= (int)c;
            }
        }
        pick = __shfl_sync(0xffffffffu, pick, sl);
        r    = __shfl_sync(0xffffffffu, newr, sl);
        prefix |= pick << shift;
    }
    // keep iff key >= prefix  (exactly matches reference: dots < kth -> masked, ties kept)

    // softmax over kept entries, in place; zeros elsewhere
    float sum = 0.f;
    for (int j = lane; j < JJ; j += 32) {
        float e = 0.f;
        if (j < jlen) {
            float v = srow[j];
            if (fkey(v) >= prefix) e = expf(v - m);
        }
        srow[j] = e;
        sum += e;
    }
#pragma unroll
    for (int o = 16; o; o >>= 1) sum += __shfl_xor_sync(0xffffffffu, sum, o);
    float inv = 1.0f / sum;
    for (int j = lane; j < JJ; j += 32) srow[j] *= inv;

    __syncthreads();

    // post-softmax talking heads: attn2[kk][j] = sum_h attn[h][j] * post[h][kk]  -> g_raw
    const size_t ob = ((size_t)(b * HH) * NN + i) * JJ;
    const size_t hs = (size_t)NN * JJ;
    for (int j = tid; j < JJ; j += 512) {
        float a[HH];
#pragma unroll
        for (int hh = 0; hh < HH; hh++) a[hh] = rows[hh * JROW + j];
#pragma unroll
        for (int kk = 0; kk < HH; kk++) {
            float sacc = 0.f;
#pragma unroll
            for (int hh = 0; hh < HH; hh++) sacc += a[hh] * s_post[hh * 16 + kk];
            g_raw[ob + (size_t)kk * hs + j] = sacc;
        }
    }
}

// ---------------- kernel 6: context = attn2 @ V per (b,h), causal-bounded K loop ----------------
// grid = (1, 16 i-tiles, 64 bh); output scattered into g_ctx [b, i, h*64+d]
__global__ __launch_bounds__(256)
void av_gemm() {
    const int bh = blockIdx.z;
    const int b = bh >> 4, h = bh & 15;
    const int i0 = blockIdx.y * 64;

    const float* Ap = g_raw + ((size_t)bh * NN + i0) * JJ;
    const float* Vp = g_v + (size_t)bh * JJ * DH;
    const int kmax = min(JJ, i0 + 128);   // rows in tile attend j <= i+64 <= i0+127

    __shared__ float As[16][68];  // [k][i]
    __shared__ float Bs[16][64];  // [k][d]

    const int tid = threadIdx.x;
    const int tx = tid & 15, ty = tid >> 4;
    const int ar = tid >> 2, akq = (tid & 3) << 2;     // A loader: row 0..63, k-quad
    const int br = tid >> 4, bdq = (tid & 15) << 2;    // B loader: k-row 0..15, d-quad

    float acc[4][4];
#pragma unroll
    for (int i = 0; i < 4; i++)
#pragma unroll
        for (int j = 0; j < 4; j++) acc[i][j] = 0.f;

    for (int kt = 0; kt < kmax; kt += 16) {
        float4 a4 = *(const float4*)(Ap + (size_t)ar * JJ + kt + akq);
        float4 b4 = *(const float4*)(Vp + (size_t)(kt + br) * DH + bdq);
        __syncthreads();
        As[akq + 0][ar] = a4.x; As[akq + 1][ar] = a4.y; As[akq + 2][ar] = a4.z; As[akq + 3][ar] = a4.w;
        *(float4*)&Bs[br][bdq] = b4;
        __syncthreads();
#pragma unroll
        for (int kk = 0; kk < 16; kk++) {
            float a[4], bb[4];
#pragma unroll
            for (int i = 0; i < 4; i++) a[i] = As[kk][ty * 4 + i];
#pragma unroll
            for (int j = 0; j < 4; j++) bb[j] = Bs[kk][tx * 4 + j];
#pragma unroll
            for (int i = 0; i < 4; i++)
#pragma unroll
                for (int j = 0; j < 4; j++) acc[i][j] += a[i] * bb[j];
        }
    }

    const int irow = i0 + ty * 4;
    const int d0 = h * DH + tx * 4;
#pragma unroll
    for (int i = 0; i < 4; i++)
#pragma unroll
        for (int j = 0; j < 4; j++)
            g_ctx[((size_t)b * NN + irow + i) * DIMM + d0 + j] = acc[i][j];
}

// ---------------- host launcher ----------------
extern "C" void kernel_launch(void* const* d_in, const int* in_sizes, int n_in,
                              void* d_out, int out_size) {
    const float* x        = (const float*)d_in[0];
    const float* Wq       = (const float*)d_in[1];
    const float* Wk       = (const float*)d_in[2];
    const float* Wv       = (const float*)d_in[3];
    const float* pre_proj = (const float*)d_in[4];
    const float* post_proj= (const float*)d_in[5];
    const float* mem_k    = (const float*)d_in[6];
    const float* mem_v    = (const float*)d_in[7];
    const float* Wout     = (const float*)d_in[8];
    const float* bout     = (const float*)d_in[9];
    float* out = (float*)d_out;
    (void)in_sizes; (void)n_in; (void)out_size;

    const int topk_smem = (HH * JROW + HH * 256) * 4;  // 86,080 bytes
    cudaFuncSetAttribute(topk_kernel, cudaFuncAttributeMaxDynamicSharedMemorySize, topk_smem);

    fill_mem_kernel<<<64, 1024>>>(mem_k, mem_v);

    sgemm128<0><<<dim3(8, 32), 256>>>(x, Wq, nullptr, nullptr);
    sgemm128<1><<<dim3(8, 32), 256>>>(x, Wk, nullptr, nullptr);
    sgemm128<3><<<dim3(8, 32), 256>>>(x, Wv, nullptr, nullptr);

    dots_gemm<<<dim3(17, 16, 64), 256>>>();

    premix_kernel<<<BB * NN, 256>>>(pre_proj);

    topk_kernel<<<BB * NN, 512, topk_smem>>>(post_proj);

    av_gemm<<<dim3(1, 16, 64), 256>>>();

    sgemm128<2><<<dim3(8, 32), 256>>>(nullptr, Wout, bout, out);
}